// round 1
// baseline (speedup 1.0000x reference)
#include <cuda_runtime.h>
#include <math.h>

#define H 128
#define HP 132           // padded stride (floats)
#define NODES 64         // nodes per CTA
#define GPC 8            // graphs per CTA (8 nodes each)
#define NT 256           // threads per CTA

// shared layout (float offsets)
#define OFF_X0 0
#define OFF_A  (OFF_X0 + NODES*HP)     // 8448
#define OFF_B  (OFF_A  + NODES*HP)     // 16896
#define OFF_W  (OFF_B  + NODES*HP)     // 25344
#define OFF_G  (OFF_W  + H*HP)         // 42240
#define OFF_V0 (OFF_G  + GPC*HP)       // 43296
#define OFF_V1 (OFF_V0 + H)            // 43424
#define OFF_POS (OFF_V1 + H)           // 43552
#define OFF_D  (OFF_POS + NODES*2)     // 43680
#define OFF_INT (OFF_D + NODES*8)      // 44192
#define SMEM_FLOATS (OFF_INT + 144)    // 44336 -> 177344 bytes

__device__ __forceinline__ void load_w(float* sW, const float* __restrict__ g, int rows)
{
    const float4* g4 = (const float4*)g;
    for (int idx = threadIdx.x; idx < rows * 32; idx += NT) {
        int r = idx >> 5, c = idx & 31;
        float4 v = g4[idx];
        *(float4*)&sW[r * HP + (c << 2)] = v;
    }
}

__device__ __forceinline__ void load_vec(float* dst, const float* __restrict__ src, int n)
{
    for (int i = threadIdx.x; i < n; i += NT) dst[i] = src[i];
}

// C[64xH] = X[64xH] @ W[HxH] (+C if accumulate) (+biasScale*bias) (relu)
// all operands in shared, strides HP. 4x8 register tile per thread.
__device__ __forceinline__ void gemm(const float* __restrict__ X, const float* __restrict__ W,
                                     float* __restrict__ C, const float* __restrict__ bias,
                                     float biasScale, bool doRelu, bool accumulate)
{
    const int tx = threadIdx.x & 15;
    const int ty = threadIdx.x >> 4;
    const int r0 = ty * 4;
    const int c0 = tx * 8;
    float acc[4][8];
#pragma unroll
    for (int i = 0; i < 4; ++i)
#pragma unroll
        for (int j = 0; j < 8; ++j) acc[i][j] = 0.f;

    const float* Xp = X + r0 * HP;
#pragma unroll 2
    for (int k = 0; k < H; k += 4) {
        float xv[4][4];
#pragma unroll
        for (int i = 0; i < 4; ++i) {
            float4 t = *(const float4*)&Xp[i * HP + k];
            xv[i][0] = t.x; xv[i][1] = t.y; xv[i][2] = t.z; xv[i][3] = t.w;
        }
#pragma unroll
        for (int kk = 0; kk < 4; ++kk) {
            float4 wa = *(const float4*)&W[(k + kk) * HP + c0];
            float4 wb = *(const float4*)&W[(k + kk) * HP + c0 + 4];
            float wv[8] = {wa.x, wa.y, wa.z, wa.w, wb.x, wb.y, wb.z, wb.w};
#pragma unroll
            for (int i = 0; i < 4; ++i) {
                float x = xv[i][kk];
#pragma unroll
                for (int j = 0; j < 8; ++j) acc[i][j] = fmaf(x, wv[j], acc[i][j]);
            }
        }
    }
#pragma unroll
    for (int i = 0; i < 4; ++i) {
#pragma unroll
        for (int j = 0; j < 8; ++j) {
            float v = acc[i][j];
            if (accumulate) v += C[(r0 + i) * HP + c0 + j];
            if (bias) v += biasScale * bias[c0 + j];
            if (doRelu) v = fmaxf(v, 0.f);
            C[(r0 + i) * HP + c0 + j] = v;
        }
    }
}

__global__ __launch_bounds__(NT) void prettyrnn_kernel(
    const int* __restrict__ anchors, const int* __restrict__ n_jumps,
    const float* __restrict__ positions, const int* __restrict__ colors,
    const int* __restrict__ markers,
    const float* __restrict__ pre_W1, const float* __restrict__ pre_b1,
    const float* __restrict__ pre_W2, const float* __restrict__ pre_b2,
    const float* __restrict__ msg_W1, const float* __restrict__ msg_b1,
    const float* __restrict__ msg_W2, const float* __restrict__ msg_b2,
    const float* __restrict__ post_W1, const float* __restrict__ post_b1,
    const float* __restrict__ post_W2, const float* __restrict__ post_b2,
    const float* __restrict__ out_W1, const float* __restrict__ out_b1,
    const float* __restrict__ out_W2, const float* __restrict__ out_b2,
    float* __restrict__ out)
{
    extern __shared__ float sm[];
    float* sX0 = sm + OFF_X0;
    float* sA  = sm + OFF_A;
    float* sB  = sm + OFF_B;
    float* sW  = sm + OFF_W;
    float* sG  = sm + OFF_G;
    float* sV0 = sm + OFF_V0;
    float* sV1 = sm + OFF_V1;
    float* sPos = sm + OFF_POS;
    float* sD  = sm + OFF_D;
    int* sCol = (int*)(sm + OFF_INT);
    int* sMrk = sCol + 64;
    int* sAnc = sMrk + 64;
    int* sJmp = sAnc + 8;

    const int tid = threadIdx.x;
    const int nodeBase = blockIdx.x * NODES;
    const int graphBase = blockIdx.x * GPC;
    const int tx = tid & 15;
    const int ty = tid >> 4;
    const int r0 = ty * 4;
    const int c0 = tx * 8;

    // ---- phase 0: load per-node/graph inputs + pre_W1 + pre_b1 ----
    if (tid < NODES) {
        sCol[tid] = colors[nodeBase + tid];
        sMrk[tid] = markers[nodeBase + tid];
        sPos[2 * tid]     = positions[2 * (nodeBase + tid)];
        sPos[2 * tid + 1] = positions[2 * (nodeBase + tid) + 1];
    }
    if (tid >= NODES && tid < NODES + GPC) {
        int g = tid - NODES;
        sAnc[g] = anchors[graphBase + g];
        sJmp[g] = n_jumps[graphBase + g];
    }
    load_w(sW, pre_W1, 42);
    load_vec(sV0, pre_b1, H);
    __syncthreads();

    // ---- distances (per node, per in-graph neighbor slot) ----
    for (int idx = tid; idx < NODES * 8; idx += NT) {
        int n = idx >> 3, jj = idx & 7;
        int j = (n & ~7) + jj;
        float dx = sPos[2 * n]     - sPos[2 * j];
        float dy = sPos[2 * n + 1] - sPos[2 * j + 1];
        sD[idx] = sqrtf(dx * dx + dy * dy);
    }

    // ---- pre layer 1: one-hot gather of pre_W1 rows -> relu -> sA ----
    {
#pragma unroll
        for (int i = 0; i < 4; ++i) {
            int n = r0 + i;
            int g = n >> 3;
            float px = sPos[2 * n], py = sPos[2 * n + 1];
            const float* rw0 = sW;
            const float* rw1 = sW + HP;
            const float* rc = sW + (2 + sCol[n]) * HP;
            const float* rm = sW + (10 + (sMrk[n] - 8)) * HP;
            const float* ra = sW + (18 + sAnc[g]) * HP;
            const float* rj = sW + (34 + sJmp[g]) * HP;
#pragma unroll
            for (int c = 0; c < 8; ++c) {
                int k = c0 + c;
                float v = rc[k] + rm[k] + ra[k] + rj[k] + sV0[k];
                v = fmaf(px, rw0[k], fmaf(py, rw1[k], v));
                sA[n * HP + k] = fmaxf(v, 0.f);
            }
        }
    }
    __syncthreads();

    // ---- pre layer 2: x0 = relu stuff ... actually x0 = h1 @ pre_W2 + b2 (linear) ----
    load_w(sW, pre_W2, H); load_vec(sV0, pre_b2, H);
    __syncthreads();
    gemm(sA, sW, sX0, sV0, 1.f, false, false);   // x0 (no relu: second layer linear)
    __syncthreads();

    // ---- A = x0 @ msg_W1[0:128] ----
    load_w(sW, msg_W1, H);
    __syncthreads();
    gemm(sX0, sW, sA, nullptr, 0.f, false, false);
    __syncthreads();

    // ---- B = x0 @ msg_W1[128:256]; also w1d (row 256) + msg_b1 ----
    load_w(sW, msg_W1 + H * H, H);
    load_vec(sV0, msg_W1 + 2 * H * H, H);   // dist weight row
    load_vec(sV1, msg_b1, H);
    __syncthreads();
    gemm(sX0, sW, sB, nullptr, 0.f, false, false);
    __syncthreads();

    // ---- edge aggregation: s[n] = sum_{j!=n} relu(A[n]+B[j]+d*w1d+b1) (in place -> sA) ----
    {
        float wv[8], bv[8];
        {
            float4 a0 = *(const float4*)&sV0[c0]; float4 a1 = *(const float4*)&sV0[c0 + 4];
            wv[0]=a0.x; wv[1]=a0.y; wv[2]=a0.z; wv[3]=a0.w; wv[4]=a1.x; wv[5]=a1.y; wv[6]=a1.z; wv[7]=a1.w;
            float4 b0 = *(const float4*)&sV1[c0]; float4 b1 = *(const float4*)&sV1[c0 + 4];
            bv[0]=b0.x; bv[1]=b0.y; bv[2]=b0.z; bv[3]=b0.w; bv[4]=b1.x; bv[5]=b1.y; bv[6]=b1.z; bv[7]=b1.w;
        }
#pragma unroll
        for (int i = 0; i < 4; ++i) {
            int n = r0 + i, nb = n & ~7, nloc = n & 7;
            float a[8];
            {
                float4 a0 = *(const float4*)&sA[n * HP + c0];
                float4 a1 = *(const float4*)&sA[n * HP + c0 + 4];
                a[0]=a0.x; a[1]=a0.y; a[2]=a0.z; a[3]=a0.w; a[4]=a1.x; a[5]=a1.y; a[6]=a1.z; a[7]=a1.w;
            }
            float s[8] = {0,0,0,0,0,0,0,0};
#pragma unroll
            for (int jj = 0; jj < 8; ++jj) {
                if (jj == nloc) continue;
                float d = sD[n * 8 + jj];
                const float* bp = sB + (nb + jj) * HP + c0;
                float4 b0 = *(const float4*)bp;
                float4 b1 = *(const float4*)(bp + 4);
                float bb[8] = {b0.x, b0.y, b0.z, b0.w, b1.x, b1.y, b1.z, b1.w};
#pragma unroll
                for (int c = 0; c < 8; ++c) {
                    float t = a[c] + bb[c] + fmaf(d, wv[c], bv[c]);
                    s[c] += fmaxf(t, 0.f);
                }
            }
            *(float4*)&sA[n * HP + c0]     = make_float4(s[0], s[1], s[2], s[3]);
            *(float4*)&sA[n * HP + c0 + 4] = make_float4(s[4], s[5], s[6], s[7]);
        }
    }
    __syncthreads();

    // ---- upd = s @ msg_W2 + 7*msg_b2 -> sB ----
    load_w(sW, msg_W2, H); load_vec(sV0, msg_b2, H);
    __syncthreads();
    gemm(sA, sW, sB, sV0, 7.f, false, false);
    __syncthreads();

    // ---- post layer 1 (two passes): h = relu(upd@P1a + x0@P1b + b1) -> sA ----
    load_w(sW, post_W1, H);
    __syncthreads();
    gemm(sB, sW, sA, nullptr, 0.f, false, false);
    __syncthreads();
    load_w(sW, post_W1 + H * H, H); load_vec(sV0, post_b1, H);
    __syncthreads();
    gemm(sX0, sW, sA, sV0, 1.f, true, true);
    __syncthreads();

    // ---- post layer 2: x = h @ post_W2 + b2 -> sB ----
    load_w(sW, post_W2, H); load_vec(sV0, post_b2, H);
    __syncthreads();
    gemm(sA, sW, sB, sV0, 1.f, false, false);
    __syncthreads();

    // ---- graph sum -> sG ----
    for (int idx = tid; idx < GPC * H; idx += NT) {
        int g = idx >> 7, k = idx & (H - 1);
        float s = 0.f;
#pragma unroll
        for (int i = 0; i < 8; ++i) s += sB[(g * 8 + i) * HP + k];
        sG[g * HP + k] = s;
    }
    __syncthreads();

    // ---- out layer 1: ho = relu(g @ out_W1 + b1) -> sA rows 0..7 ----
    load_w(sW, out_W1, H); load_vec(sV0, out_b1, H);
    __syncthreads();
    for (int idx = tid; idx < GPC * H; idx += NT) {
        int g = idx >> 7, k = idx & (H - 1);
        float s = sV0[k];
#pragma unroll 8
        for (int kk = 0; kk < H; ++kk) s = fmaf(sG[g * HP + kk], sW[kk * HP + k], s);
        sA[g * HP + k] = fmaxf(s, 0.f);
    }
    __syncthreads();

    // ---- out layer 2: logits = ho @ out_W2 + b2 -> gmem ----
    load_vec(sW, out_W2, H * 16);
    load_vec(sV1, out_b2, 16);
    __syncthreads();
    if (tid < GPC * 16) {
        int g = tid >> 4, o = tid & 15;
        float s = sV1[o];
#pragma unroll 8
        for (int k = 0; k < H; ++k) s = fmaf(sA[g * HP + k], sW[k * 16 + o], s);
        out[(graphBase + g) * 16 + o] = s;
    }
}

extern "C" void kernel_launch(void* const* d_in, const int* in_sizes, int n_in,
                              void* d_out, int out_size)
{
    const int*   anchors   = (const int*)d_in[0];
    const int*   n_jumps   = (const int*)d_in[1];
    const float* positions = (const float*)d_in[2];
    const int*   colors    = (const int*)d_in[3];
    const int*   markers   = (const int*)d_in[4];
    const float* pre_W1  = (const float*)d_in[5];
    const float* pre_b1  = (const float*)d_in[6];
    const float* pre_W2  = (const float*)d_in[7];
    const float* pre_b2  = (const float*)d_in[8];
    const float* msg_W1  = (const float*)d_in[9];
    const float* msg_b1  = (const float*)d_in[10];
    const float* msg_W2  = (const float*)d_in[11];
    const float* msg_b2  = (const float*)d_in[12];
    const float* post_W1 = (const float*)d_in[13];
    const float* post_b1 = (const float*)d_in[14];
    const float* post_W2 = (const float*)d_in[15];
    const float* post_b2 = (const float*)d_in[16];
    const float* out_W1  = (const float*)d_in[17];
    const float* out_b1  = (const float*)d_in[18];
    const float* out_W2  = (const float*)d_in[19];
    const float* out_b2  = (const float*)d_in[20];

    int bs = in_sizes[0];
    int blocks = bs / GPC;
    size_t smemBytes = SMEM_FLOATS * sizeof(float);
    cudaFuncSetAttribute(prettyrnn_kernel,
                         cudaFuncAttributeMaxDynamicSharedMemorySize, (int)smemBytes);
    prettyrnn_kernel<<<blocks, NT, smemBytes>>>(
        anchors, n_jumps, positions, colors, markers,
        pre_W1, pre_b1, pre_W2, pre_b2,
        msg_W1, msg_b1, msg_W2, msg_b2,
        post_W1, post_b1, post_W2, post_b2,
        out_W1, out_b1, out_W2, out_b2,
        (float*)d_out);
}

// round 4
// speedup vs baseline: 1.6763x; 1.6763x over previous
#include <cuda_runtime.h>
#include <cstdint>
#include <math.h>

#define H 128
#define AP 132           // activation stride (floats) -> conflict-free A-frag LDS
#define WP 128           // weight stride (floats), XOR-swizzled columns
#define NODES 64         // nodes per CTA
#define GPC 8            // graphs per CTA
#define NT 256

// shared layout (float offsets)
#define OFF_X0 0
#define OFF_A  (OFF_X0 + NODES*AP)
#define OFF_B  (OFF_A  + NODES*AP)
#define OFF_W  (OFF_B  + NODES*AP)
#define OFF_G  (OFF_W  + H*WP)
#define OFF_V0 (OFF_G  + GPC*AP)
#define OFF_V1 (OFF_V0 + H)
#define OFF_POS (OFF_V1 + H)
#define OFF_D  (OFF_POS + NODES*2)
#define OFF_INT (OFF_D + NODES*8)
#define SMEM_FLOATS (OFF_INT + 160)

__device__ __forceinline__ uint32_t f2tf32(float f) {
    uint32_t r;
    asm("cvt.rna.tf32.f32 %0, %1;" : "=r"(r) : "f"(f));
    return r;
}
// split fp32 -> (hi, lo) tf32 pair
__device__ __forceinline__ void tf32_split(float f, uint32_t& hi, uint32_t& lo) {
    hi = f2tf32(f);
    lo = f2tf32(f - __uint_as_float(hi));
}

// ---- weight staging: cp.async with XOR column swizzle (for mma B-frag loads) ----
__device__ __forceinline__ void load_w_sw(float* sW, const float* __restrict__ gw)
{
    uint32_t sbase = (uint32_t)__cvta_generic_to_shared(sW);
    for (int idx = threadIdx.x; idx < H * 32; idx += NT) {
        int r = idx >> 5, c4 = idx & 31;
        int dst = r * WP + (((c4 << 2)) ^ ((r & 3) << 3));   // swizzle 8-col blocks, 16B-safe
        asm volatile("cp.async.ca.shared.global [%0], [%1], 16;"
                     :: "r"(sbase + dst * 4), "l"(gw + idx * 4));
    }
    asm volatile("cp.async.commit_group;");
}
__device__ __forceinline__ void cp_wait() { asm volatile("cp.async.wait_group 0;"); }

// plain contiguous staging (SIMT-consumed weights)
__device__ __forceinline__ void load_w_plain(float* sW, const float* __restrict__ g, int rows)
{
    const float4* g4 = (const float4*)g;
    for (int idx = threadIdx.x; idx < rows * 32; idx += NT)
        *(float4*)&sW[idx * 4] = g4[idx];
}

__device__ __forceinline__ void load_vec(float* dst, const float* __restrict__ src, int n)
{
    for (int i = threadIdx.x; i < n; i += NT) dst[i] = src[i];
}

__device__ __forceinline__ void mma_tf32(float* c, const uint32_t* a, const uint32_t* b)
{
    asm volatile(
        "mma.sync.aligned.m16n8k8.row.col.f32.tf32.tf32.f32 "
        "{%0,%1,%2,%3}, {%4,%5,%6,%7}, {%8,%9}, {%0,%1,%2,%3};"
        : "+f"(c[0]), "+f"(c[1]), "+f"(c[2]), "+f"(c[3])
        : "r"(a[0]), "r"(a[1]), "r"(a[2]), "r"(a[3]), "r"(b[0]), "r"(b[1]));
}

// C[64xH] = X[64xH] @ W[HxH]; X fp32 (stride AP), W fp32 swizzled (stride WP).
// 3xTF32 compensated: hi*hi + lo*hi + hi*lo per tile -> ~fp32 accuracy.
// 8 warps, 2x4 warp grid, each warp 32x32 output (2 m-tiles x 4 n-tiles of m16n8k8).
__device__ __forceinline__ void gemm_mma(const float* __restrict__ X, const float* __restrict__ W,
                                         float* __restrict__ C, const float* __restrict__ bias,
                                         float biasScale, bool doRelu, bool accumulate)
{
    const int lane = threadIdx.x & 31;
    const int warp = threadIdx.x >> 5;
    const int wm = warp & 1, wn = warp >> 1;
    const int m0 = wm * 32, n0 = wn * 32;
    const int g = lane >> 2, tig = lane & 3;
    const int xr = tig << 3;                 // swizzle xor for this thread's k-phase

    float acc[2][4][4];
#pragma unroll
    for (int mt = 0; mt < 2; ++mt)
#pragma unroll
        for (int nt = 0; nt < 4; ++nt)
#pragma unroll
            for (int i = 0; i < 4; ++i) acc[mt][nt][i] = 0.f;

#pragma unroll 2
    for (int k0 = 0; k0 < H; k0 += 8) {
        uint32_t ah[2][4], al[2][4];
#pragma unroll
        for (int mt = 0; mt < 2; ++mt) {
            int r = m0 + mt * 16 + g;
            tf32_split(X[r * AP + k0 + tig],           ah[mt][0], al[mt][0]);
            tf32_split(X[(r + 8) * AP + k0 + tig],     ah[mt][1], al[mt][1]);
            tf32_split(X[r * AP + k0 + tig + 4],       ah[mt][2], al[mt][2]);
            tf32_split(X[(r + 8) * AP + k0 + tig + 4], ah[mt][3], al[mt][3]);
        }
        uint32_t bh[4][2], bl[4][2];
#pragma unroll
        for (int nt = 0; nt < 4; ++nt) {
            int c = (n0 + nt * 8 + g) ^ xr;
            tf32_split(W[(k0 + tig) * WP + c],     bh[nt][0], bl[nt][0]);
            tf32_split(W[(k0 + tig + 4) * WP + c], bh[nt][1], bl[nt][1]);
        }
#pragma unroll
        for (int mt = 0; mt < 2; ++mt)
#pragma unroll
            for (int nt = 0; nt < 4; ++nt) {
                mma_tf32(acc[mt][nt], ah[mt], bh[nt]);
                mma_tf32(acc[mt][nt], al[mt], bh[nt]);
                mma_tf32(acc[mt][nt], ah[mt], bl[nt]);
            }
    }

#pragma unroll
    for (int mt = 0; mt < 2; ++mt) {
#pragma unroll
        for (int nt = 0; nt < 4; ++nt) {
            int r = m0 + mt * 16 + g;
            int c = n0 + nt * 8 + 2 * tig;
#pragma unroll
            for (int h = 0; h < 2; ++h) {       // h=0: rows r ; h=1: rows r+8
                int rr = r + h * 8;
#pragma unroll
                for (int q = 0; q < 2; ++q) {   // col c, c+1
                    float v = acc[mt][nt][h * 2 + q];
                    int off = rr * AP + c + q;
                    if (accumulate) v += C[off];
                    if (bias) v += biasScale * bias[c + q];
                    if (doRelu) v = fmaxf(v, 0.f);
                    C[off] = v;
                }
            }
        }
    }
}

__global__ __launch_bounds__(NT) void prettyrnn_kernel(
    const int* __restrict__ anchors, const int* __restrict__ n_jumps,
    const float* __restrict__ positions, const int* __restrict__ colors,
    const int* __restrict__ markers,
    const float* __restrict__ pre_W1, const float* __restrict__ pre_b1,
    const float* __restrict__ pre_W2, const float* __restrict__ pre_b2,
    const float* __restrict__ msg_W1, const float* __restrict__ msg_b1,
    const float* __restrict__ msg_W2, const float* __restrict__ msg_b2,
    const float* __restrict__ post_W1, const float* __restrict__ post_b1,
    const float* __restrict__ post_W2, const float* __restrict__ post_b2,
    const float* __restrict__ out_W1, const float* __restrict__ out_b1,
    const float* __restrict__ out_W2, const float* __restrict__ out_b2,
    float* __restrict__ out)
{
    extern __shared__ float sm[];
    float* sX0 = sm + OFF_X0;
    float* sA  = sm + OFF_A;
    float* sB  = sm + OFF_B;
    float* sW  = sm + OFF_W;
    float* sG  = sm + OFF_G;
    float* sV0 = sm + OFF_V0;
    float* sV1 = sm + OFF_V1;
    float* sPos = sm + OFF_POS;
    float* sD  = sm + OFF_D;
    int* sCol = (int*)(sm + OFF_INT);
    int* sMrk = sCol + 64;
    int* sAnc = sMrk + 64;
    int* sJmp = sAnc + 8;

    const int tid = threadIdx.x;
    const int nodeBase = blockIdx.x * NODES;
    const int graphBase = blockIdx.x * GPC;
    const int tx = tid & 15;
    const int ty = tid >> 4;
    const int r0 = ty * 4;
    const int c0 = tx * 8;

    // ---- phase 0: inputs + pre_W1 (plain) + pre_b1 ----
    if (tid < NODES) {
        sCol[tid] = colors[nodeBase + tid];
        sMrk[tid] = markers[nodeBase + tid];
        sPos[2 * tid]     = positions[2 * (nodeBase + tid)];
        sPos[2 * tid + 1] = positions[2 * (nodeBase + tid) + 1];
    }
    if (tid >= NODES && tid < NODES + GPC) {
        int g = tid - NODES;
        sAnc[g] = anchors[graphBase + g];
        sJmp[g] = n_jumps[graphBase + g];
    }
    load_w_plain(sW, pre_W1, 42);
    load_vec(sV0, pre_b1, H);
    __syncthreads();

    // ---- distances ----
    for (int idx = tid; idx < NODES * 8; idx += NT) {
        int n = idx >> 3, jj = idx & 7;
        int j = (n & ~7) + jj;
        float dx = sPos[2 * n]     - sPos[2 * j];
        float dy = sPos[2 * n + 1] - sPos[2 * j + 1];
        sD[idx] = sqrtf(dx * dx + dy * dy);
    }

    // ---- pre layer 1 (one-hot gather, SIMT) -> sA (fp32, relu) ----
    {
#pragma unroll
        for (int i = 0; i < 4; ++i) {
            int n = r0 + i;
            int g = n >> 3;
            float px = sPos[2 * n], py = sPos[2 * n + 1];
            const float* rw0 = sW;
            const float* rw1 = sW + WP;
            const float* rc = sW + (2 + sCol[n]) * WP;
            const float* rm = sW + (10 + (sMrk[n] - 8)) * WP;
            const float* ra = sW + (18 + sAnc[g]) * WP;
            const float* rj = sW + (34 + sJmp[g]) * WP;
#pragma unroll
            for (int c = 0; c < 8; ++c) {
                int k = c0 + c;
                float v = rc[k] + rm[k] + ra[k] + rj[k] + sV0[k];
                v = fmaf(px, rw0[k], fmaf(py, rw1[k], v));
                sA[n * AP + k] = fmaxf(v, 0.f);
            }
        }
    }
    __syncthreads();

    // ---- pre layer 2 (linear): x0 = h1 @ pre_W2 + b2 -> sX0 ----
    load_w_sw(sW, pre_W2);
    load_vec(sV0, pre_b2, H);
    cp_wait(); __syncthreads();
    gemm_mma(sA, sW, sX0, sV0, 1.f, false, false);
    __syncthreads();

    // ---- A = x0 @ msg_W1[0:128] -> sA ----
    load_w_sw(sW, msg_W1);
    cp_wait(); __syncthreads();
    gemm_mma(sX0, sW, sA, nullptr, 0.f, false, false);
    __syncthreads();

    // ---- B = x0 @ msg_W1[128:256] -> sB; w1d row + msg_b1 ----
    load_w_sw(sW, msg_W1 + H * H);
    load_vec(sV0, msg_W1 + 2 * H * H, H);
    load_vec(sV1, msg_b1, H);
    cp_wait(); __syncthreads();
    gemm_mma(sX0, sW, sB, nullptr, 0.f, false, false);
    __syncthreads();

    // ---- edge aggregation: s[n] = sum_{j!=n} relu(A[n]+B[j]+d*w1d+b1) -> sA ----
    {
        float wv[8], bv[8];
        {
            float4 a0 = *(const float4*)&sV0[c0]; float4 a1 = *(const float4*)&sV0[c0 + 4];
            wv[0]=a0.x; wv[1]=a0.y; wv[2]=a0.z; wv[3]=a0.w; wv[4]=a1.x; wv[5]=a1.y; wv[6]=a1.z; wv[7]=a1.w;
            float4 b0 = *(const float4*)&sV1[c0]; float4 b1 = *(const float4*)&sV1[c0 + 4];
            bv[0]=b0.x; bv[1]=b0.y; bv[2]=b0.z; bv[3]=b0.w; bv[4]=b1.x; bv[5]=b1.y; bv[6]=b1.z; bv[7]=b1.w;
        }
#pragma unroll
        for (int i = 0; i < 4; ++i) {
            int n = r0 + i, nb = n & ~7, nloc = n & 7;
            float a[8];
            {
                float4 a0 = *(const float4*)&sA[n * AP + c0];
                float4 a1 = *(const float4*)&sA[n * AP + c0 + 4];
                a[0]=a0.x; a[1]=a0.y; a[2]=a0.z; a[3]=a0.w; a[4]=a1.x; a[5]=a1.y; a[6]=a1.z; a[7]=a1.w;
            }
            float s[8] = {0,0,0,0,0,0,0,0};
#pragma unroll
            for (int jj = 0; jj < 8; ++jj) {
                if (jj == nloc) continue;
                float d = sD[n * 8 + jj];
                const float* bp = sB + (nb + jj) * AP + c0;
                float4 b0 = *(const float4*)bp;
                float4 b1 = *(const float4*)(bp + 4);
                float bb[8] = {b0.x, b0.y, b0.z, b0.w, b1.x, b1.y, b1.z, b1.w};
#pragma unroll
                for (int c = 0; c < 8; ++c) {
                    float t = a[c] + bb[c] + fmaf(d, wv[c], bv[c]);
                    s[c] += fmaxf(t, 0.f);
                }
            }
            *(float4*)&sA[n * AP + c0]     = make_float4(s[0], s[1], s[2], s[3]);
            *(float4*)&sA[n * AP + c0 + 4] = make_float4(s[4], s[5], s[6], s[7]);
        }
    }
    __syncthreads();

    // ---- upd = s @ msg_W2 + 7*msg_b2 -> sB ----
    load_w_sw(sW, msg_W2);
    load_vec(sV0, msg_b2, H);
    cp_wait(); __syncthreads();
    gemm_mma(sA, sW, sB, sV0, 7.f, false, false);
    __syncthreads();

    // ---- post layer 1, pass a: sA = upd @ P1a (partial) ----
    load_w_sw(sW, post_W1);
    cp_wait(); __syncthreads();
    gemm_mma(sB, sW, sA, nullptr, 0.f, false, false);
    __syncthreads();

    // ---- post layer 1, pass b: sA = relu(sA + x0 @ P1b + b1) ----
    load_w_sw(sW, post_W1 + H * H);
    load_vec(sV0, post_b1, H);
    cp_wait(); __syncthreads();
    gemm_mma(sX0, sW, sA, sV0, 1.f, true, true);
    __syncthreads();

    // ---- post layer 2: x = h @ post_W2 + b2 -> sB ----
    load_w_sw(sW, post_W2);
    load_vec(sV0, post_b2, H);
    cp_wait(); __syncthreads();
    gemm_mma(sA, sW, sB, sV0, 1.f, false, false);
    __syncthreads();

    // ---- graph sum -> sG ----
    for (int idx = tid; idx < GPC * H; idx += NT) {
        int g = idx >> 7, k = idx & (H - 1);
        float s = 0.f;
#pragma unroll
        for (int i = 0; i < 8; ++i) s += sB[(g * 8 + i) * AP + k];
        sG[g * AP + k] = s;
    }
    __syncthreads();

    // ---- out layer 1 (SIMT): ho = relu(g @ out_W1 + b1) -> sA rows 0..7 ----
    load_w_plain(sW, out_W1, H);
    load_vec(sV0, out_b1, H);
    __syncthreads();
    for (int idx = tid; idx < GPC * H; idx += NT) {
        int g = idx >> 7, k = idx & (H - 1);
        float s = sV0[k];
#pragma unroll 8
        for (int kk = 0; kk < H; ++kk) s = fmaf(sG[g * AP + kk], sW[kk * WP + k], s);
        sA[g * AP + k] = fmaxf(s, 0.f);
    }
    __syncthreads();

    // ---- out layer 2 (SIMT): logits -> gmem ----
    load_vec(sW, out_W2, H * 16);
    load_vec(sV1, out_b2, 16);
    __syncthreads();
    if (tid < GPC * 16) {
        int g = tid >> 4, o = tid & 15;
        float s = sV1[o];
#pragma unroll 8
        for (int k = 0; k < H; ++k) s = fmaf(sA[g * AP + k], sW[k * 16 + o], s);
        out[(graphBase + g) * 16 + o] = s;
    }
}

extern "C" void kernel_launch(void* const* d_in, const int* in_sizes, int n_in,
                              void* d_out, int out_size)
{
    const int*   anchors   = (const int*)d_in[0];
    const int*   n_jumps   = (const int*)d_in[1];
    const float* positions = (const float*)d_in[2];
    const int*   colors    = (const int*)d_in[3];
    const int*   markers   = (const int*)d_in[4];
    const float* pre_W1  = (const float*)d_in[5];
    const float* pre_b1  = (const float*)d_in[6];
    const float* pre_W2  = (const float*)d_in[7];
    const float* pre_b2  = (const float*)d_in[8];
    const float* msg_W1  = (const float*)d_in[9];
    const float* msg_b1  = (const float*)d_in[10];
    const float* msg_W2  = (const float*)d_in[11];
    const float* msg_b2  = (const float*)d_in[12];
    const float* post_W1 = (const float*)d_in[13];
    const float* post_b1 = (const float*)d_in[14];
    const float* post_W2 = (const float*)d_in[15];
    const float* post_b2 = (const float*)d_in[16];
    const float* out_W1  = (const float*)d_in[17];
    const float* out_b1  = (const float*)d_in[18];
    const float* out_W2  = (const float*)d_in[19];
    const float* out_b2  = (const float*)d_in[20];

    int bs = in_sizes[0];
    int blocks = bs / GPC;
    size_t smemBytes = SMEM_FLOATS * sizeof(float);
    cudaFuncSetAttribute(prettyrnn_kernel,
                         cudaFuncAttributeMaxDynamicSharedMemorySize, (int)smemBytes);
    prettyrnn_kernel<<<blocks, NT, smemBytes>>>(
        anchors, n_jumps, positions, colors, markers,
        pre_W1, pre_b1, pre_W2, pre_b2,
        msg_W1, msg_b1, msg_W2, msg_b2,
        post_W1, post_b1, post_W2, post_b2,
        out_W1, out_b1, out_W2, out_b2,
        (float*)d_out);
}

// round 6
// speedup vs baseline: 1.7835x; 1.0640x over previous
#include <cuda_runtime.h>
#include <cstdint>
#include <math.h>

#define H 128
#define AP 132           // activation stride (floats) -> conflict-free A-frag LDS
#define WP 128           // weight stride (floats), XOR-swizzled columns
#define KC 64            // k-chunk rows per weight stage
#define NODES 32         // nodes per CTA
#define GPC 4            // graphs per CTA
#define NT 128

// shared layout (float offsets)
#define OFF_X0 0
#define OFF_A  (OFF_X0 + NODES*AP)     // 4224
#define OFF_B  (OFF_A  + NODES*AP)     // 8448
#define OFF_W  (OFF_B  + NODES*AP)     // 12672  (KC*WP = 8192 floats)
#define OFF_G  (OFF_W  + KC*WP)        // 20864
#define OFF_V0 (OFF_G  + GPC*AP)       // 21392
#define OFF_V1 (OFF_V0 + H)            // 21520
#define OFF_POS (OFF_V1 + H)           // 21648
#define OFF_D  (OFF_POS + NODES*2)     // 21712
#define OFF_INT (OFF_D + NODES*8)      // 21968
#define SMEM_FLOATS (OFF_INT + 96)     // 22064 -> 88256 bytes (~86 KB, 2 CTAs/SM)

__device__ __forceinline__ uint32_t f2tf32(float f) {
    uint32_t r;
    asm("cvt.rna.tf32.f32 %0, %1;" : "=r"(r) : "f"(f));
    return r;
}
// split fp32 -> (hi, lo); lo passed as raw fp32 bits (MMA truncates, error ~2^-23)
__device__ __forceinline__ void tf32_split(float f, uint32_t& hi, uint32_t& lo) {
    hi = f2tf32(f);
    lo = __float_as_uint(f - __uint_as_float(hi));
}

// ---- weight chunk staging: cp.async, KC rows of 128, XOR column swizzle ----
__device__ __forceinline__ void load_w_sw(float* sW, const float* __restrict__ gw)
{
    uint32_t sbase = (uint32_t)__cvta_generic_to_shared(sW);
    for (int idx = threadIdx.x; idx < KC * 32; idx += NT) {
        int r = idx >> 5, c4 = idx & 31;
        int dst = r * WP + (((c4 << 2)) ^ ((r & 3) << 3));
        asm volatile("cp.async.ca.shared.global [%0], [%1], 16;"
                     :: "r"(sbase + dst * 4), "l"(gw + idx * 4));
    }
    asm volatile("cp.async.commit_group;");
}
__device__ __forceinline__ void cp_wait() { asm volatile("cp.async.wait_group 0;"); }

// plain contiguous staging (SIMT-consumed weights)
__device__ __forceinline__ void load_w_plain(float* sW, const float* __restrict__ g, int rows)
{
    const float4* g4 = (const float4*)g;
    for (int idx = threadIdx.x; idx < rows * 32; idx += NT)
        *(float4*)&sW[idx * 4] = g4[idx];
}

__device__ __forceinline__ void load_vec(float* dst, const float* __restrict__ src, int n)
{
    for (int i = threadIdx.x; i < n; i += NT) dst[i] = src[i];
}

__device__ __forceinline__ void mma_tf32(float* c, const uint32_t* a, const uint32_t* b)
{
    asm volatile(
        "mma.sync.aligned.m16n8k8.row.col.f32.tf32.tf32.f32 "
        "{%0,%1,%2,%3}, {%4,%5,%6,%7}, {%8,%9}, {%0,%1,%2,%3};"
        : "+f"(c[0]), "+f"(c[1]), "+f"(c[2]), "+f"(c[3])
        : "r"(a[0]), "r"(a[1]), "r"(a[2]), "r"(a[3]), "r"(b[0]), "r"(b[1]));
}

// half-K gemm pass: acc += X[:, kbase:kbase+KC] @ Wchunk  (3xTF32 compensated)
// 4 warps, warp w covers cols w*32..w*32+31, rows 0..31 (2 m-tiles x 4 n-tiles m16n8k8)
__device__ __forceinline__ void gemm_half(const float* __restrict__ X, const float* __restrict__ W,
                                          int kbase, float acc[2][4][4])
{
    const int lane = threadIdx.x & 31;
    const int warp = threadIdx.x >> 5;
    const int n0 = warp * 32;
    const int g = lane >> 2, tig = lane & 3;
    const int xr = tig << 3;

#pragma unroll 2
    for (int kc = 0; kc < KC; kc += 8) {
        const int k0 = kbase + kc;
        uint32_t ah[2][4], al[2][4];
#pragma unroll
        for (int mt = 0; mt < 2; ++mt) {
            int r = mt * 16 + g;
            tf32_split(X[r * AP + k0 + tig],           ah[mt][0], al[mt][0]);
            tf32_split(X[(r + 8) * AP + k0 + tig],     ah[mt][1], al[mt][1]);
            tf32_split(X[r * AP + k0 + tig + 4],       ah[mt][2], al[mt][2]);
            tf32_split(X[(r + 8) * AP + k0 + tig + 4], ah[mt][3], al[mt][3]);
        }
        uint32_t bh[4][2], bl[4][2];
#pragma unroll
        for (int nt = 0; nt < 4; ++nt) {
            int c = (n0 + nt * 8 + g) ^ xr;
            tf32_split(W[(kc + tig) * WP + c],     bh[nt][0], bl[nt][0]);
            tf32_split(W[(kc + tig + 4) * WP + c], bh[nt][1], bl[nt][1]);
        }
#pragma unroll
        for (int mt = 0; mt < 2; ++mt)
#pragma unroll
            for (int nt = 0; nt < 4; ++nt) {
                mma_tf32(acc[mt][nt], ah[mt], bh[nt]);
                mma_tf32(acc[mt][nt], al[mt], bh[nt]);
                mma_tf32(acc[mt][nt], ah[mt], bl[nt]);
            }
    }
}

__device__ __forceinline__ void gemm_epi(float acc[2][4][4], float* __restrict__ C,
                                         const float* __restrict__ bias, float biasScale,
                                         bool doRelu, bool accumulate)
{
    const int lane = threadIdx.x & 31;
    const int warp = threadIdx.x >> 5;
    const int n0 = warp * 32;
    const int g = lane >> 2, tig = lane & 3;
#pragma unroll
    for (int mt = 0; mt < 2; ++mt) {
#pragma unroll
        for (int nt = 0; nt < 4; ++nt) {
            int r = mt * 16 + g;
            int c = n0 + nt * 8 + 2 * tig;
#pragma unroll
            for (int h = 0; h < 2; ++h) {
                int rr = r + h * 8;
#pragma unroll
                for (int q = 0; q < 2; ++q) {
                    float v = acc[mt][nt][h * 2 + q];
                    int off = rr * AP + c + q;
                    if (accumulate) v += C[off];
                    if (bias) v += biasScale * bias[c + q];
                    if (doRelu) v = fmaxf(v, 0.f);
                    C[off] = v;
                }
            }
        }
    }
}

// full gemm stage: chunked weight staging, acc persistent across chunks
#define GEMM_STAGE(X, GW, C, BIASG, BSCALE, RELU, ACCUM) do {          \
    float acc[2][4][4];                                                \
    _Pragma("unroll")                                                  \
    for (int _m = 0; _m < 2; ++_m)                                     \
        _Pragma("unroll")                                              \
        for (int _n = 0; _n < 4; ++_n)                                 \
            _Pragma("unroll")                                          \
            for (int _i = 0; _i < 4; ++_i) acc[_m][_n][_i] = 0.f;      \
    load_w_sw(sW, (GW));                                               \
    if ((BIASG) != nullptr) load_vec(sV0, (BIASG), H);                 \
    cp_wait(); __syncthreads();                                        \
    gemm_half((X), sW, 0, acc);                                        \
    __syncthreads();                                                   \
    load_w_sw(sW, (GW) + KC * H);                                      \
    cp_wait(); __syncthreads();                                        \
    gemm_half((X), sW, KC, acc);                                       \
    gemm_epi(acc, (C), (BIASG) ? sV0 : nullptr, (BSCALE), (RELU), (ACCUM)); \
    __syncthreads();                                                   \
} while (0)

__global__ __launch_bounds__(NT) void prettyrnn_kernel(
    const int* __restrict__ anchors, const int* __restrict__ n_jumps,
    const float* __restrict__ positions, const int* __restrict__ colors,
    const int* __restrict__ markers,
    const float* __restrict__ pre_W1, const float* __restrict__ pre_b1,
    const float* __restrict__ pre_W2, const float* __restrict__ pre_b2,
    const float* __restrict__ msg_W1, const float* __restrict__ msg_b1,
    const float* __restrict__ msg_W2, const float* __restrict__ msg_b2,
    const float* __restrict__ post_W1, const float* __restrict__ post_b1,
    const float* __restrict__ post_W2, const float* __restrict__ post_b2,
    const float* __restrict__ out_W1, const float* __restrict__ out_b1,
    const float* __restrict__ out_W2, const float* __restrict__ out_b2,
    float* __restrict__ out)
{
    extern __shared__ float sm[];
    float* sX0 = sm + OFF_X0;
    float* sA  = sm + OFF_A;
    float* sB  = sm + OFF_B;
    float* sW  = sm + OFF_W;
    float* sG  = sm + OFF_G;
    float* sV0 = sm + OFF_V0;
    float* sV1 = sm + OFF_V1;
    float* sPos = sm + OFF_POS;
    float* sD  = sm + OFF_D;
    int* sCol = (int*)(sm + OFF_INT);
    int* sMrk = sCol + NODES;
    int* sAnc = sMrk + NODES;
    int* sJmp = sAnc + GPC;

    const int tid = threadIdx.x;
    const int nodeBase = blockIdx.x * NODES;
    const int graphBase = blockIdx.x * GPC;
    const int tx = tid & 15;
    const int ty = tid >> 4;
    const int r0 = ty * 4;          // 8 ty * 4 rows = 32 rows
    const int c0 = tx * 8;          // 16 tx * 8 cols = 128 cols

    // ---- phase 0: inputs + pre_W1 (plain, 42 rows) + pre_b1 ----
    if (tid < NODES) {
        sCol[tid] = colors[nodeBase + tid];
        sMrk[tid] = markers[nodeBase + tid];
        sPos[2 * tid]     = positions[2 * (nodeBase + tid)];
        sPos[2 * tid + 1] = positions[2 * (nodeBase + tid) + 1];
    }
    if (tid >= NODES && tid < NODES + GPC) {
        int g = tid - NODES;
        sAnc[g] = anchors[graphBase + g];
        sJmp[g] = n_jumps[graphBase + g];
    }
    load_w_plain(sW, pre_W1, 42);
    load_vec(sV0, pre_b1, H);
    __syncthreads();

    // ---- distances ----
    for (int idx = tid; idx < NODES * 8; idx += NT) {
        int n = idx >> 3, jj = idx & 7;
        int j = (n & ~7) + jj;
        float dx = sPos[2 * n]     - sPos[2 * j];
        float dy = sPos[2 * n + 1] - sPos[2 * j + 1];
        sD[idx] = sqrtf(dx * dx + dy * dy);
    }

    // ---- pre layer 1 (one-hot gather, SIMT) -> sA (fp32, relu) ----
    {
#pragma unroll
        for (int i = 0; i < 4; ++i) {
            int n = r0 + i;
            int g = n >> 3;
            float px = sPos[2 * n], py = sPos[2 * n + 1];
            const float* rw0 = sW;
            const float* rw1 = sW + WP;
            const float* rc = sW + (2 + sCol[n]) * WP;
            const float* rm = sW + (10 + (sMrk[n] - 8)) * WP;
            const float* ra = sW + (18 + sAnc[g]) * WP;
            const float* rj = sW + (34 + sJmp[g]) * WP;
#pragma unroll
            for (int c = 0; c < 8; ++c) {
                int k = c0 + c;
                float v = rc[k] + rm[k] + ra[k] + rj[k] + sV0[k];
                v = fmaf(px, rw0[k], fmaf(py, rw1[k], v));
                sA[n * AP + k] = fmaxf(v, 0.f);
            }
        }
    }
    __syncthreads();

    // ---- pre layer 2 (linear): x0 = h1 @ pre_W2 + b2 -> sX0 ----
    GEMM_STAGE(sA, pre_W2, sX0, pre_b2, 1.f, false, false);

    // ---- A = x0 @ msg_W1[0:128] -> sA ----
    GEMM_STAGE(sX0, msg_W1, sA, (const float*)nullptr, 0.f, false, false);

    // ---- B = x0 @ msg_W1[128:256] -> sB; also dist row + msg_b1 (manual loads) ----
    {
        float acc[2][4][4];
#pragma unroll
        for (int _m = 0; _m < 2; ++_m)
#pragma unroll
            for (int _n = 0; _n < 4; ++_n)
#pragma unroll
                for (int _i = 0; _i < 4; ++_i) acc[_m][_n][_i] = 0.f;
        load_w_sw(sW, msg_W1 + H * H);
        load_vec(sV0, msg_W1 + 2 * H * H, H);   // dist weight row
        load_vec(sV1, msg_b1, H);
        cp_wait(); __syncthreads();
        gemm_half(sX0, sW, 0, acc);
        __syncthreads();
        load_w_sw(sW, msg_W1 + H * H + KC * H);
        cp_wait(); __syncthreads();
        gemm_half(sX0, sW, KC, acc);
        gemm_epi(acc, sB, nullptr, 0.f, false, false);
        __syncthreads();
    }

    // ---- edge aggregation: s[n] = sum_{j!=n} relu(A[n]+B[j]+d*w1d+b1) -> sA ----
    {
        float wv[8], bv[8];
        {
            float4 a0 = *(const float4*)&sV0[c0]; float4 a1 = *(const float4*)&sV0[c0 + 4];
            wv[0]=a0.x; wv[1]=a0.y; wv[2]=a0.z; wv[3]=a0.w; wv[4]=a1.x; wv[5]=a1.y; wv[6]=a1.z; wv[7]=a1.w;
            float4 b0 = *(const float4*)&sV1[c0]; float4 b1 = *(const float4*)&sV1[c0 + 4];
            bv[0]=b0.x; bv[1]=b0.y; bv[2]=b0.z; bv[3]=b0.w; bv[4]=b1.x; bv[5]=b1.y; bv[6]=b1.z; bv[7]=b1.w;
        }
#pragma unroll
        for (int i = 0; i < 4; ++i) {
            int n = r0 + i, nb = n & ~7, nloc = n & 7;
            float a[8];
            {
                float4 a0 = *(const float4*)&sA[n * AP + c0];
                float4 a1 = *(const float4*)&sA[n * AP + c0 + 4];
                a[0]=a0.x; a[1]=a0.y; a[2]=a0.z; a[3]=a0.w; a[4]=a1.x; a[5]=a1.y; a[6]=a1.z; a[7]=a1.w;
            }
            float s[8] = {0,0,0,0,0,0,0,0};
#pragma unroll
            for (int jj = 0; jj < 8; ++jj) {
                if (jj == nloc) continue;
                float d = sD[n * 8 + jj];
                const float* bp = sB + (nb + jj) * AP + c0;
                float4 b0 = *(const float4*)bp;
                float4 b1 = *(const float4*)(bp + 4);
                float bb[8] = {b0.x, b0.y, b0.z, b0.w, b1.x, b1.y, b1.z, b1.w};
#pragma unroll
                for (int c = 0; c < 8; ++c) {
                    float t = a[c] + bb[c] + fmaf(d, wv[c], bv[c]);
                    s[c] += fmaxf(t, 0.f);
                }
            }
            *(float4*)&sA[n * AP + c0]     = make_float4(s[0], s[1], s[2], s[3]);
            *(float4*)&sA[n * AP + c0 + 4] = make_float4(s[4], s[5], s[6], s[7]);
        }
    }
    __syncthreads();

    // ---- upd = s @ msg_W2 + 7*msg_b2 -> sB ----
    GEMM_STAGE(sA, msg_W2, sB, msg_b2, 7.f, false, false);

    // ---- post layer 1, pass a: sA = upd @ P1a (partial) ----
    GEMM_STAGE(sB, post_W1, sA, (const float*)nullptr, 0.f, false, false);

    // ---- post layer 1, pass b: sA = relu(sA + x0 @ P1b + b1) ----
    GEMM_STAGE(sX0, post_W1 + H * H, sA, post_b1, 1.f, true, true);

    // ---- post layer 2: x = h @ post_W2 + b2 -> sB ----
    GEMM_STAGE(sA, post_W2, sB, post_b2, 1.f, false, false);

    // ---- graph sum -> sG ----
    for (int idx = tid; idx < GPC * H; idx += NT) {
        int g = idx >> 7, k = idx & (H - 1);
        float s = 0.f;
#pragma unroll
        for (int i = 0; i < 8; ++i) s += sB[(g * 8 + i) * AP + k];
        sG[g * AP + k] = s;
    }
    __syncthreads();

    // ---- out layer 1 (SIMT, k-split): ho = relu(g @ out_W1 + b1) -> sA rows 0..3 ----
    {
        float part[(GPC * H + NT - 1) / NT];   // 4 per thread
        load_w_plain(sW, out_W1, KC);          // rows 0..63
        load_vec(sV0, out_b1, H);
        __syncthreads();
        {
            int ii = 0;
            for (int idx = tid; idx < GPC * H; idx += NT, ++ii) {
                int g = idx >> 7, k = idx & (H - 1);
                float s = sV0[k];
#pragma unroll 8
                for (int kk = 0; kk < KC; ++kk) s = fmaf(sG[g * AP + kk], sW[kk * WP + k], s);
                part[ii] = s;
            }
        }
        __syncthreads();
        load_w_plain(sW, out_W1 + KC * H, KC); // rows 64..127
        __syncthreads();
        {
            int ii = 0;
            for (int idx = tid; idx < GPC * H; idx += NT, ++ii) {
                int g = idx >> 7, k = idx & (H - 1);
                float s = part[ii];
#pragma unroll 8
                for (int kk = 0; kk < KC; ++kk) s = fmaf(sG[g * AP + KC + kk], sW[kk * WP + k], s);
                sA[g * AP + k] = fmaxf(s, 0.f);
            }
        }
        __syncthreads();
    }

    // ---- out layer 2 (SIMT): logits -> gmem ----
    load_vec(sW, out_W2, H * 16);
    load_vec(sV1, out_b2, 16);
    __syncthreads();
    if (tid < GPC * 16) {
        int g = tid >> 4, o = tid & 15;
        float s = sV1[o];
#pragma unroll 8
        for (int k = 0; k < H; ++k) s = fmaf(sA[g * AP + k], sW[k * 16 + o], s);
        out[(graphBase + g) * 16 + o] = s;
    }
}

extern "C" void kernel_launch(void* const* d_in, const int* in_sizes, int n_in,
                              void* d_out, int out_size)
{
    const int*   anchors   = (const int*)d_in[0];
    const int*   n_jumps   = (const int*)d_in[1];
    const float* positions = (const float*)d_in[2];
    const int*   colors    = (const int*)d_in[3];
    const int*   markers   = (const int*)d_in[4];
    const float* pre_W1  = (const float*)d_in[5];
    const float* pre_b1  = (const float*)d_in[6];
    const float* pre_W2  = (const float*)d_in[7];
    const float* pre_b2  = (const float*)d_in[8];
    const float* msg_W1  = (const float*)d_in[9];
    const float* msg_b1  = (const float*)d_in[10];
    const float* msg_W2  = (const float*)d_in[11];
    const float* msg_b2  = (const float*)d_in[12];
    const float* post_W1 = (const float*)d_in[13];
    const float* post_b1 = (const float*)d_in[14];
    const float* post_W2 = (const float*)d_in[15];
    const float* post_b2 = (const float*)d_in[16];
    const float* out_W1  = (const float*)d_in[17];
    const float* out_b1  = (const float*)d_in[18];
    const float* out_W2  = (const float*)d_in[19];
    const float* out_b2  = (const float*)d_in[20];

    int bs = in_sizes[0];
    int blocks = bs / GPC;
    size_t smemBytes = SMEM_FLOATS * sizeof(float);
    cudaFuncSetAttribute(prettyrnn_kernel,
                         cudaFuncAttributeMaxDynamicSharedMemorySize, (int)smemBytes);
    prettyrnn_kernel<<<blocks, NT, smemBytes>>>(
        anchors, n_jumps, positions, colors, markers,
        pre_W1, pre_b1, pre_W2, pre_b2,
        msg_W1, msg_b1, msg_W2, msg_b2,
        post_W1, post_b1, post_W2, post_b2,
        out_W1, out_b1, out_W2, out_b2,
        (float*)d_out);
}